// round 5
// baseline (speedup 1.0000x reference)
#include <cuda_runtime.h>
#include <math.h>

// Shapes (fixed by the problem)
#define B 32
#define C 256
#define H 64
#define W 64
#define HW (H*W)            // 4096
#define PLANES (B*C)        // 8192
#define RH 3                // int(0.05*64)
#define RW 6                // int(0.1*64)
#define CLAMP_SX 61.0f      // h - rh
#define CLAMP_SY 58.0f      // w - rw

#define THREADS 512
#define PPB 2               // planes per block
#define NB (C / PPB)        // 128 blocks per batch
#define GRID (B * NB)       // 4096 blocks

// Scratch (no cudaMalloc allowed). Zero-initialized at module load;
// the kernel resets its own counters at batch completion, so every
// graph replay starts clean.
__device__ float g_mean[PLANES];
__device__ float g_scale[PLANES];
__device__ int   g_sx[PLANES];
__device__ int   g_sy[PLANES];
__device__ int   g_ctr1[B];   // phase-1 arrivals (2 per block -> 256)
__device__ int   g_flag[B];   // MLP results published
__device__ int   g_ctr2[B];   // completion arrivals (1 per block -> 128)

__device__ __forceinline__ float sigmoidf_acc(float v) {
    return 1.0f / (1.0f + expf(-v));
}
__device__ __forceinline__ float warp_red(float s) {
#pragma unroll
    for (int o = 16; o; o >>= 1) s += __shfl_xor_sync(0xffffffffu, s, o);
    return s;
}

__global__ void __launch_bounds__(THREADS, 3) k_fused(
    const float* __restrict__ x, float* __restrict__ out,
    const float* __restrict__ se_w1,   // (16,256)
    const float* __restrict__ se_w2,   // (256,16)
    const float* __restrict__ ch_w, const float* __restrict__ ch_b,
    const float* __restrict__ cw_w, const float* __restrict__ cw_b,
    const float* __restrict__ dh_fc1w, const float* __restrict__ dh_fc1b,
    const float* __restrict__ dh_fc2w, const float* __restrict__ dh_fc2b,
    const float* __restrict__ dw_fc1w, const float* __restrict__ dw_fc1b,
    const float* __restrict__ dw_fc2w, const float* __restrict__ dw_fc2b)
{
    __shared__ float4 tile[PPB * (HW / 4)];   // 32 KB: 2 planes cached on-SM
    __shared__ float red[16];
    __shared__ float yv[256];
    __shared__ float t1[16];
    __shared__ float gv[256];
    __shared__ float vh[256];
    __shared__ float th1[64];
    __shared__ float th2[1024];
    __shared__ int   isLast;

    const int bid   = blockIdx.x;
    const int batch = bid / NB;     // consecutive bids cover one batch (wave-safe)
    const int sub   = bid % NB;
    const int tid   = threadIdx.x;
    const int half  = tid >> 8;     // which of the 2 planes this thread serves
    const int t     = tid & 255;
    const int wid   = tid >> 5;     // 0..15
    const int lane  = tid & 31;

    if (tid == 0) isLast = 0;

    // ---------------- Phase 1: load planes to SMEM + compute means ----------
    const int plane = batch * C + sub * PPB + half;
    const float4* xp = reinterpret_cast<const float4*>(x) + (size_t)plane * (HW / 4);
    float4* sp = tile + half * (HW / 4);

    float s = 0.f;
#pragma unroll
    for (int i = 0; i < 4; i++) {
        float4 v = xp[t + i * 256];
        sp[t + i * 256] = v;
        s += (v.x + v.y) + (v.z + v.w);
    }
    s = warp_red(s);
    if (lane == 0) red[wid] = s;
    __syncthreads();

    if (tid < PPB) {
        float tot = 0.f;
#pragma unroll
        for (int i = 0; i < 8; i++) tot += red[tid * 8 + i];
        g_mean[batch * C + sub * PPB + tid] = tot * (1.0f / (float)HW);
        __threadfence();                       // publish mean (release)
        int old = atomicAdd(&g_ctr1[batch], 1);
        if (old == NB * PPB - 1) isLast = 1;   // this block saw the last arrival
    }
    __syncthreads();

    // ---------------- Phase 2: last arriver runs the batch MLP --------------
    if (isLast) {
        __threadfence();  // acquire: all g_mean of this batch now visible

        if (tid < 256) yv[tid] = g_mean[batch * C + tid];
        __syncthreads();

        // SE squeeze: t1[16] = relu(y @ se_w1^T), one output per warp
        {
            const float* r = se_w1 + wid * 256;
            float acc = 0.f;
#pragma unroll
            for (int k = 0; k < 8; k++) acc = fmaf(yv[lane + k * 32], r[lane + k * 32], acc);
            acc = warp_red(acc);
            if (lane == 0) t1[wid] = fmaxf(acc, 0.f);
        }
        __syncthreads();

        // SE excite: scale + gated mean
        if (tid < 256) {
            const float4* r = reinterpret_cast<const float4*>(se_w2 + tid * 16);
            const float4* tt = reinterpret_cast<const float4*>(t1);
            float acc = 0.f;
#pragma unroll
            for (int j = 0; j < 4; j++) {
                float4 wv = r[j], tv = tt[j];
                acc = fmaf(wv.x, tv.x, fmaf(wv.y, tv.y, fmaf(wv.z, tv.z, fmaf(wv.w, tv.w, acc))));
            }
            float sg = sigmoidf_acc(acc);
            g_scale[batch * C + tid] = sg;
            gv[tid] = yv[tid] * sg;
        }
        __syncthreads();

        // Two dyrelu branches, sequential (16 warps each)
        for (int br = 0; br < 2; br++) {
            const float* cw   = br ? cw_w    : ch_w;
            const float* cb   = br ? cw_b    : ch_b;
            const float* fc1w = br ? dw_fc1w : dh_fc1w;
            const float* fc1b = br ? dw_fc1b : dh_fc1b;
            const float* fc2w = br ? dw_fc2w : dh_fc2w;
            const float* fc2b = br ? dw_fc2b : dh_fc2b;
            int* outArr  = br ? g_sy : g_sx;
            float clampv = br ? CLAMP_SY : CLAMP_SX;

            // vh[256] = gv @ cw^T + cb : 16 outputs per warp
#pragma unroll 4
            for (int i = 0; i < 16; i++) {
                int o = wid * 16 + i;
                const float* r = cw + o * 256;
                float acc = 0.f;
#pragma unroll
                for (int k = 0; k < 8; k++) acc = fmaf(gv[lane + k * 32], r[lane + k * 32], acc);
                acc = warp_red(acc);
                if (lane == 0) vh[o] = acc + cb[o];
            }
            __syncthreads();

            // th1[64] = relu(vh @ fc1w^T + fc1b) : 4 outputs per warp
#pragma unroll
            for (int i = 0; i < 4; i++) {
                int o = wid * 4 + i;
                const float* r = fc1w + o * 256;
                float acc = 0.f;
#pragma unroll
                for (int k = 0; k < 8; k++) acc = fmaf(vh[lane + k * 32], r[lane + k * 32], acc);
                acc = warp_red(acc);
                if (lane == 0) th1[o] = fmaxf(acc + fc1b[o], 0.f);
            }
            __syncthreads();

            float t1a = th1[lane * 2];
            float t1b = th1[lane * 2 + 1];

            // th2[1024] = fc2(th1) : 64 outputs per warp
#pragma unroll 4
            for (int i = 0; i < 64; i++) {
                int m = wid * 64 + i;
                float2 wv = reinterpret_cast<const float2*>(fc2w + m * 64)[lane];
                float acc = fmaf(t1a, wv.x, t1b * wv.y);
                acc = warp_red(acc);
                if (lane == 0) th2[m] = acc + fc2b[m];
            }
            __syncthreads();

            // per-channel dyrelu + sigmoid + ceil/clamp
            if (tid < 256) {
                float v  = vh[tid];
                float u0 = 2.0f * sigmoidf_acc(th2[tid * 4 + 0]) - 1.0f;
                float u1 = 2.0f * sigmoidf_acc(th2[tid * 4 + 1]) - 1.0f;
                float u2 = 2.0f * sigmoidf_acc(th2[tid * 4 + 2]) - 1.0f;
                float u3 = 2.0f * sigmoidf_acc(th2[tid * 4 + 3]) - 1.0f;
                float a0 = u0 + 1.0f, a1 = u1;
                float b0 = 0.5f * u2, b1 = 0.5f * u3;
                float dy = fmaxf(fmaf(v, a0, b0), fmaf(v, a1, b1));
                float sg = sigmoidf_acc(dy);
                outArr[batch * C + tid] = (int)fminf(ceilf(64.0f * sg), clampv);
            }
            __syncthreads();   // before smem reuse by next branch
        }

        __threadfence();                        // publish scale/sx/sy
        if (tid == 0) atomicExch(&g_flag[batch], 1);
    } else {
        // ---------------- spin until this batch's MLP is published ----------
        if (tid == 0) {
            while (atomicAdd(&g_flag[batch], 0) == 0) __nanosleep(64);
            __threadfence();                    // acquire
        }
        __syncthreads();
    }

    // ---------------- Phase 3: apply scale + mask from SMEM -----------------
    {
        float sc = g_scale[plane];
        int sxv = g_sx[plane];
        int syv = g_sy[plane];
        float4* op = reinterpret_cast<float4*>(out) + (size_t)plane * (HW / 4);

#pragma unroll
        for (int i = 0; i < 4; i++) {
            int p = t + i * 256;
            int e = p * 4;
            int row = e >> 6;
            int col = e & 63;
            float4 v = sp[p];
            v.x *= sc; v.y *= sc; v.z *= sc; v.w *= sc;
            if (row >= sxv && row < sxv + RH) {
                if (col + 0 >= syv && col + 0 < syv + RW) v.x = 0.f;
                if (col + 1 >= syv && col + 1 < syv + RW) v.y = 0.f;
                if (col + 2 >= syv && col + 2 < syv + RW) v.z = 0.f;
                if (col + 3 >= syv && col + 3 < syv + RW) v.w = 0.f;
            }
            op[p] = v;
        }
    }

    // ---------------- Completion: last block resets per-batch state ---------
    __syncthreads();
    if (tid == 0) {
        int o2 = atomicAdd(&g_ctr2[batch], 1);
        if (o2 == NB - 1) {
            g_ctr1[batch] = 0;
            g_flag[batch] = 0;
            g_ctr2[batch] = 0;
        }
    }
}

// ---------------------------------------------------------------------------
extern "C" void kernel_launch(void* const* d_in, const int* in_sizes, int n_in,
                              void* d_out, int out_size) {
    const float* x       = (const float*)d_in[0];
    const float* se_w1   = (const float*)d_in[1];
    const float* se_w2   = (const float*)d_in[2];
    const float* ch_w    = (const float*)d_in[3];
    const float* ch_b    = (const float*)d_in[4];
    const float* cw_w    = (const float*)d_in[5];
    const float* cw_b    = (const float*)d_in[6];
    const float* dh_fc1w = (const float*)d_in[7];
    const float* dh_fc1b = (const float*)d_in[8];
    const float* dh_fc2w = (const float*)d_in[9];
    const float* dh_fc2b = (const float*)d_in[10];
    const float* dw_fc1w = (const float*)d_in[11];
    const float* dw_fc1b = (const float*)d_in[12];
    const float* dw_fc2w = (const float*)d_in[13];
    const float* dw_fc2b = (const float*)d_in[14];
    float* out = (float*)d_out;

    k_fused<<<GRID, THREADS>>>(x, out,
                               se_w1, se_w2, ch_w, ch_b, cw_w, cw_b,
                               dh_fc1w, dh_fc1b, dh_fc2w, dh_fc2b,
                               dw_fc1w, dw_fc1b, dw_fc2w, dw_fc2b);
}

// round 7
// speedup vs baseline: 3.9421x; 3.9421x over previous
#include <cuda_runtime.h>
#include <math.h>

// Shapes (fixed by the problem)
#define B 32
#define C 256
#define H 64
#define W 64
#define HW (H*W)            // 4096
#define PLANES (B*C)        // 8192
#define RH 3                // int(0.05*64)
#define RW 6                // int(0.1*64)
#define CLAMP_SX 61.0f      // h - rh
#define CLAMP_SY 58.0f      // w - rw

#define GROUPS 2
#define BPG (B / GROUPS)            // 16 batches per group
#define PLANES_PG (BPG * C)         // 4096 planes per group (67 MB of x)

// Scratch (no cudaMalloc allowed)
__device__ float g_mean[PLANES];
__device__ float g_scale[PLANES];
__device__ int   g_sx[PLANES];
__device__ int   g_sy[PLANES];

// ---------------------------------------------------------------------------
// Kernel 1: per-(b,c) mean over one plane. One block per plane, 256 threads.
// Default (ld.ca) loads: x slice ALLOCATES in L2 and stays resident for
// this group's k_apply (67MB slice << 126MB L2).
// ---------------------------------------------------------------------------
__global__ void k_mean(const float* __restrict__ x, int plane0) {
    int plane = plane0 + blockIdx.x;
    const float4* xp = reinterpret_cast<const float4*>(x) + (size_t)plane * (HW / 4);
    int tid = threadIdx.x;

    float s = 0.f;
#pragma unroll
    for (int i = 0; i < 4; i++) {
        float4 v = xp[tid + i * 256];
        s += (v.x + v.y) + (v.z + v.w);
    }
#pragma unroll
    for (int o = 16; o; o >>= 1) s += __shfl_xor_sync(0xffffffffu, s, o);

    __shared__ float ws[8];
    if ((tid & 31) == 0) ws[tid >> 5] = s;
    __syncthreads();
    if (tid == 0) {
        float t = 0.f;
#pragma unroll
        for (int i = 0; i < 8; i++) t += ws[i];
        g_mean[plane] = t * (1.0f / (float)HW);
    }
}

// ---------------------------------------------------------------------------
// Kernel 2: MLP math, warp-per-output reductions, 512 threads = 16 warps.
// grid = (BPG, 2): blockIdx.x = batch within group, blockIdx.y = branch.
// ---------------------------------------------------------------------------
__device__ __forceinline__ float sigmoidf_acc(float v) {
    return 1.0f / (1.0f + expf(-v));
}

__device__ __forceinline__ float warp_red(float s) {
#pragma unroll
    for (int o = 16; o; o >>= 1) s += __shfl_xor_sync(0xffffffffu, s, o);
    return s;
}

__global__ void __launch_bounds__(512) k_mlp(
    int batch0,
    const float* __restrict__ se_w1,   // (16,256)
    const float* __restrict__ se_w2,   // (256,16)
    const float* __restrict__ ch_w, const float* __restrict__ ch_b,
    const float* __restrict__ cw_w, const float* __restrict__ cw_b,
    const float* __restrict__ dh_fc1w, const float* __restrict__ dh_fc1b,
    const float* __restrict__ dh_fc2w, const float* __restrict__ dh_fc2b,
    const float* __restrict__ dw_fc1w, const float* __restrict__ dw_fc1b,
    const float* __restrict__ dw_fc2w, const float* __restrict__ dw_fc2b)
{
    __shared__ float y[256];
    __shared__ float t1[16];
    __shared__ float gv[256];
    __shared__ float vh[256];
    __shared__ float th1[64];
    __shared__ float th2[1024];

    int b    = batch0 + blockIdx.x;
    int br   = blockIdx.y;
    int tid  = threadIdx.x;
    int wid  = tid >> 5;          // 0..15
    int lane = tid & 31;

    const float* cw   = br ? cw_w    : ch_w;
    const float* cb   = br ? cw_b    : ch_b;
    const float* fc1w = br ? dw_fc1w : dh_fc1w;
    const float* fc1b = br ? dw_fc1b : dh_fc1b;
    const float* fc2w = br ? dw_fc2w : dh_fc2w;
    const float* fc2b = br ? dw_fc2b : dh_fc2b;
    int* outArr = br ? g_sy : g_sx;
    float clampv = br ? CLAMP_SY : CLAMP_SX;

    if (tid < 256) y[tid] = g_mean[b * 256 + tid];
    __syncthreads();

    float yreg[8];
#pragma unroll
    for (int k = 0; k < 8; k++) yreg[k] = y[lane + k * 32];

    // SE squeeze: 1 output per warp
    {
        const float* r = se_w1 + wid * 256;
        float s = 0.f;
#pragma unroll
        for (int k = 0; k < 8; k++) s = fmaf(yreg[k], r[lane + k * 32], s);
        s = warp_red(s);
        if (lane == 0) t1[wid] = fmaxf(s, 0.f);
    }
    __syncthreads();

    // SE excite
    if (tid < 256) {
        const float4* r = reinterpret_cast<const float4*>(se_w2 + tid * 16);
        const float4* t = reinterpret_cast<const float4*>(t1);
        float s = 0.f;
#pragma unroll
        for (int j = 0; j < 4; j++) {
            float4 wv = r[j];
            float4 tv = t[j];
            s = fmaf(wv.x, tv.x, fmaf(wv.y, tv.y, fmaf(wv.z, tv.z, fmaf(wv.w, tv.w, s))));
        }
        float sg = sigmoidf_acc(s);
        if (br == 0) g_scale[b * 256 + tid] = sg;
        gv[tid] = y[tid] * sg;
    }
    __syncthreads();

    float greg[8];
#pragma unroll
    for (int k = 0; k < 8; k++) greg[k] = gv[lane + k * 32];

    // vh[256] = gv @ cw^T + cb : 16 outputs per warp
#pragma unroll 4
    for (int i = 0; i < 16; i++) {
        int o = wid * 16 + i;
        const float* r = cw + o * 256;
        float s = 0.f;
#pragma unroll
        for (int k = 0; k < 8; k++) s = fmaf(greg[k], r[lane + k * 32], s);
        s = warp_red(s);
        if (lane == 0) vh[o] = s + cb[o];
    }
    __syncthreads();

    float vreg[8];
#pragma unroll
    for (int k = 0; k < 8; k++) vreg[k] = vh[lane + k * 32];

    // th1[64] = relu(vh @ fc1w^T + fc1b) : 4 outputs per warp
#pragma unroll
    for (int i = 0; i < 4; i++) {
        int o = wid * 4 + i;
        const float* r = fc1w + o * 256;
        float s = 0.f;
#pragma unroll
        for (int k = 0; k < 8; k++) s = fmaf(vreg[k], r[lane + k * 32], s);
        s = warp_red(s);
        if (lane == 0) th1[o] = fmaxf(s + fc1b[o], 0.f);
    }
    __syncthreads();

    float t1a = th1[lane * 2];
    float t1b = th1[lane * 2 + 1];

    // th2[1024] = fc2(th1): 64 outputs per warp (unroll 8 to overlap SHFL chains)
#pragma unroll 8
    for (int i = 0; i < 64; i++) {
        int m = wid * 64 + i;
        float2 wv = reinterpret_cast<const float2*>(fc2w + m * 64)[lane];
        float s = fmaf(t1a, wv.x, t1b * wv.y);
        s = warp_red(s);
        if (lane == 0) th2[m] = s + fc2b[m];
    }
    __syncthreads();

    // dyrelu + sigmoid + ceil/clamp
    if (tid < 256) {
        float v = vh[tid];
        float u0 = 2.0f * sigmoidf_acc(th2[tid * 4 + 0]) - 1.0f;
        float u1 = 2.0f * sigmoidf_acc(th2[tid * 4 + 1]) - 1.0f;
        float u2 = 2.0f * sigmoidf_acc(th2[tid * 4 + 2]) - 1.0f;
        float u3 = 2.0f * sigmoidf_acc(th2[tid * 4 + 3]) - 1.0f;
        float a0 = u0 + 1.0f, a1 = u1;
        float b0 = 0.5f * u2, b1 = 0.5f * u3;
        float dy = fmaxf(fmaf(v, a0, b0), fmaf(v, a1, b1));
        float sg = sigmoidf_acc(dy);
        outArr[b * 256 + tid] = (int)fminf(ceilf(64.0f * sg), clampv);
    }
}

// ---------------------------------------------------------------------------
// Kernel 3: out = x * scale * !inside. One block per plane, float4 I/O.
// Runs right after its group's mean: the 67MB x slice is L2-resident, so
// reads are L2 hits. Writes are __stwt (write-through, no L2 allocation):
// pure DRAM write stream that never evicts the x slice.
// ---------------------------------------------------------------------------
__global__ void k_apply(const float* __restrict__ x, float* __restrict__ out,
                        int plane0) {
    int plane = plane0 + blockIdx.x;
    float sc = g_scale[plane];
    int sx = g_sx[plane];
    int sy = g_sy[plane];

    const float4* xp = reinterpret_cast<const float4*>(x) + (size_t)plane * (HW / 4);
    float4* op = reinterpret_cast<float4*>(out) + (size_t)plane * (HW / 4);
    int tid = threadIdx.x;

#pragma unroll
    for (int i = 0; i < 4; i++) {
        int p = tid + i * 256;       // float4 index within plane
        int e = p * 4;
        int row = e >> 6;
        int col = e & 63;
        float4 v = xp[p];
        v.x *= sc; v.y *= sc; v.z *= sc; v.w *= sc;
        if (row >= sx && row < sx + RH) {
            if (col + 0 >= sy && col + 0 < sy + RW) v.x = 0.f;
            if (col + 1 >= sy && col + 1 < sy + RW) v.y = 0.f;
            if (col + 2 >= sy && col + 2 < sy + RW) v.z = 0.f;
            if (col + 3 >= sy && col + 3 < sy + RW) v.w = 0.f;
        }
        __stwt(op + p, v);
    }
}

// ---------------------------------------------------------------------------
// Single-stream, 2-group L2 pipeline:
//   mean_0 -> mlp_0 -> apply_0 -> mean_1 -> mlp_1 -> apply_1
// Each apply reads its x slice from L2 (loaded by the preceding mean).
// ---------------------------------------------------------------------------
extern "C" void kernel_launch(void* const* d_in, const int* in_sizes, int n_in,
                              void* d_out, int out_size) {
    const float* x       = (const float*)d_in[0];
    const float* se_w1   = (const float*)d_in[1];
    const float* se_w2   = (const float*)d_in[2];
    const float* ch_w    = (const float*)d_in[3];
    const float* ch_b    = (const float*)d_in[4];
    const float* cw_w    = (const float*)d_in[5];
    const float* cw_b    = (const float*)d_in[6];
    const float* dh_fc1w = (const float*)d_in[7];
    const float* dh_fc1b = (const float*)d_in[8];
    const float* dh_fc2w = (const float*)d_in[9];
    const float* dh_fc2b = (const float*)d_in[10];
    const float* dw_fc1w = (const float*)d_in[11];
    const float* dw_fc1b = (const float*)d_in[12];
    const float* dw_fc2w = (const float*)d_in[13];
    const float* dw_fc2b = (const float*)d_in[14];
    float* out = (float*)d_out;

    for (int g = 0; g < GROUPS; g++) {
        int plane0 = g * PLANES_PG;
        int batch0 = g * BPG;

        k_mean<<<PLANES_PG, 256>>>(x, plane0);

        dim3 mg(BPG, 2);
        k_mlp<<<mg, 512>>>(batch0,
                           se_w1, se_w2, ch_w, ch_b, cw_w, cw_b,
                           dh_fc1w, dh_fc1b, dh_fc2w, dh_fc2b,
                           dw_fc1w, dw_fc1b, dw_fc2w, dw_fc2b);

        k_apply<<<PLANES_PG, 256>>>(x, out, plane0);
    }
}